// round 8
// baseline (speedup 1.0000x reference)
#include <cuda_runtime.h>
#include <cuda_bf16.h>
#include <cstdint>

// ============================================================================
// Problem constants
// ============================================================================
#define B_DIM   256
#define T_DIM   2048
#define K_DIM   64
#define H_DIM   128
#define TILE_T  32
#define N_TILES (T_DIM / TILE_T)   // 64

// Scan: y_t = 0.9*y_{t-1} - 1.25*th_{t-1} + g_t, th = tanh(y), spk = .5th+.5
// g = 2.5*ff - 1.5  (2.5 folded into W, bias' = 2.5b - 1.5)

// ============================================================================
// SMEM layout (bytes)
//   [0, 27648)         x ring: 3 slots x 9216 (hi 4608 + lo 4608), 32x144B
//   [27648, 46080)     W_lo persistent (128 x 144 B)
//   [46080, 113664)    ff ring: 2 slots x 33792; each slot = 2 K-half planes
//                      of 16896 B ([t][h] stride 132 floats)
//   W_hi (init only) aliases ff region at 46080.
// ============================================================================
#define WSTR      72
#define ROWB      144
#define XBUF(s)   ((s) * 9216)
#define SMEM_W_LO 27648
#define SMEM_FF   46080
#define FFB(s)    (SMEM_FF + (s) * 33792)
#define FF_PLANE  16896
#define FF_STR    132
#define SMEM_W_HI 46080
#define SMEM_TOTAL 113664

// Named barriers (384 threads): FFREADY(s)=1+s, FFFREE(s)=3+s (s in {0,1}),
// XREADY(sx)=5+sx, XFREE(sx)=8+sx (sx in {0,1,2}), 13 = producer-only (256)
#define BAR_SYNC(id)   asm volatile("bar.sync %0, 384;"   :: "r"(id) : "memory")
#define BAR_ARRIVE(id) asm volatile("bar.arrive %0, 384;" :: "r"(id) : "memory")

// ============================================================================
// Helpers
// ============================================================================
__device__ __forceinline__ uint32_t smem_to_u32(const void* p) {
    uint32_t a;
    asm("{ .reg .u64 t; cvta.to.shared.u64 t, %1; cvt.u32.u64 %0, t; }"
        : "=r"(a) : "l"(p));
    return a;
}
__device__ __forceinline__ float tanhf_approx(float x) {
    float y; asm("tanh.approx.f32 %0, %1;" : "=f"(y) : "f"(x)); return y;
}
__device__ __forceinline__ void ldm_x4(uint32_t* r, uint32_t addr) {
    asm volatile("ldmatrix.sync.aligned.m8n8.x4.shared.b16 {%0,%1,%2,%3}, [%4];"
        : "=r"(r[0]), "=r"(r[1]), "=r"(r[2]), "=r"(r[3]) : "r"(addr));
}
__device__ __forceinline__ void mma_bf16(float* d, const uint32_t* a, const uint32_t* b) {
    asm volatile(
        "mma.sync.aligned.m16n8k16.row.col.f32.bf16.bf16.f32 "
        "{%0,%1,%2,%3},{%4,%5,%6,%7},{%8,%9},{%0,%1,%2,%3};"
        : "+f"(d[0]), "+f"(d[1]), "+f"(d[2]), "+f"(d[3])
        : "r"(a[0]), "r"(a[1]), "r"(a[2]), "r"(a[3]), "r"(b[0]), "r"(b[1]));
}
__device__ __forceinline__ uint32_t pack_bf16(__nv_bfloat16 a, __nv_bfloat16 b) {
    return ((uint32_t)__bfloat16_as_ushort(b) << 16) | __bfloat16_as_ushort(a);
}
__device__ __forceinline__ void cvt_pack(float4 v, uint2& hi, uint2& lo) {
    __nv_bfloat16 h0 = __float2bfloat16(v.x);
    __nv_bfloat16 h1 = __float2bfloat16(v.y);
    __nv_bfloat16 h2 = __float2bfloat16(v.z);
    __nv_bfloat16 h3 = __float2bfloat16(v.w);
    __nv_bfloat16 l0 = __float2bfloat16(v.x - __bfloat162float(h0));
    __nv_bfloat16 l1 = __float2bfloat16(v.y - __bfloat162float(h1));
    __nv_bfloat16 l2 = __float2bfloat16(v.z - __bfloat162float(h2));
    __nv_bfloat16 l3 = __float2bfloat16(v.w - __bfloat162float(h3));
    hi.x = pack_bf16(h0, h1); hi.y = pack_bf16(h2, h3);
    lo.x = pack_bf16(l0, l1); lo.y = pack_bf16(l2, l3);
}

// consumer-side: convert xr regs -> x ring slot s
__device__ __forceinline__ void convert_to_slot(char* smem, int s, int ct,
                                                const float4* xr) {
#pragma unroll
    for (int q = 0; q < 4; ++q) {
        int idx = ct + (q << 7);
        int row = idx >> 4, c4 = idx & 15;
        uint32_t off = (uint32_t)row * ROWB + c4 * 8;
        uint2 hi, lo; cvt_pack(xr[q], hi, lo);
        *reinterpret_cast<uint2*>(smem + XBUF(s) + off)        = hi;
        *reinterpret_cast<uint2*>(smem + XBUF(s) + 4608 + off) = lo;
    }
}

// ============================================================================
// Warp-specialized kernel. 1 CTA / batch, 384 threads.
//   tid 0..127  : consumers — tanh scan (thread = head) + x load/convert
//   tid 128..383: producers — 8 warps: (mw = heads/32) x (kh = K-half),
//                 each 32h x 32t x K32 slice, d[2][4] = 8 accumulator chains
// ============================================================================
__global__ void __launch_bounds__(384, 2)
snn_encoder_kernel(const float* __restrict__ x, const float* __restrict__ W,
                   const float* __restrict__ bvec, float* __restrict__ out) {
    extern __shared__ char smem[];
    const uint32_t sb = smem_to_u32(smem);
    const int tid = threadIdx.x;
    const int b   = blockIdx.x;
    const float* xb = x + (size_t)b * T_DIM * K_DIM;

    // ---- Cooperative W convert: (2.5*W) fp32 -> bf16 hi/lo (hi aliases ff)
    {
        const float4* w4 = reinterpret_cast<const float4*>(W);
        for (int idx = tid; idx < 2048; idx += 384) {
            float4 v = __ldg(&w4[idx]);
            v.x *= 2.5f; v.y *= 2.5f; v.z *= 2.5f; v.w *= 2.5f;
            int row = idx >> 4, c4 = idx & 15;
            uint32_t off = (uint32_t)row * ROWB + c4 * 8;
            uint2 hi, lo; cvt_pack(v, hi, lo);
            *reinterpret_cast<uint2*>(smem + SMEM_W_HI + off) = hi;
            *reinterpret_cast<uint2*>(smem + SMEM_W_LO + off) = lo;
        }
    }
    __syncthreads();

    if (tid >= 128) {
        // ==================== PRODUCERS (8 warps, K-split) ====================
        const int pt   = tid - 128;              // 0..255
        const int lane = pt & 31;
        const int pw   = pt >> 5;                // 0..7
        const int mw   = pw & 3;                 // heads [32mw, 32mw+32)
        const int kh   = pw >> 2;                // K-half: k in [32kh, 32kh+32)
        const int j    = lane >> 3;

        const uint32_t a_off = (uint32_t)(((j & 1) * 8 + (lane & 7)) * WSTR + ((j >> 1) * 8)) * 2;
        const uint32_t b_off = (uint32_t)(((j >> 1) * 8 + (lane & 7)) * WSTR + ((j & 1) * 8)) * 2;
        const uint32_t khoff = (uint32_t)kh * 64;        // 32 bf16 = 64 bytes
        const uint32_t aW_lo = sb + SMEM_W_LO + (uint32_t)(mw * 32) * ROWB + khoff + a_off;

        // hoist W_hi fragments for this K-half (ff ring aliases W_hi after)
        uint32_t Ahi[2][2][4];
        {
            const uint32_t aW_hi = sb + SMEM_W_HI + (uint32_t)(mw * 32) * ROWB + khoff + a_off;
#pragma unroll
            for (int mt = 0; mt < 2; ++mt)
#pragma unroll
                for (int ks = 0; ks < 2; ++ks)
                    ldm_x4(Ahi[mt][ks], aW_hi + (uint32_t)mt * 16 * ROWB + ks * 32);
        }
        asm volatile("bar.sync 13, 256;" ::: "memory");

        // bias' = 2.5*b - 1.5, applied once (kh == 0 warps only)
        const int r0 = lane >> 2;
        const int c0 = 2 * (lane & 3);
        float bias0[2] = {0.f, 0.f}, bias1[2] = {0.f, 0.f};
        if (kh == 0) {
#pragma unroll
            for (int mt = 0; mt < 2; ++mt) {
                bias0[mt] = fmaf(__ldg(&bvec[mw * 32 + mt * 16 + r0]), 2.5f, -1.5f);
                bias1[mt] = fmaf(__ldg(&bvec[mw * 32 + mt * 16 + r0 + 8]), 2.5f, -1.5f);
            }
        }

        int sx = 0, sf = 0;
        for (int i = 0; i < N_TILES; ++i) {
            BAR_SYNC(5 + sx);                    // wait x tile i converted

            float d[2][4][4];
#pragma unroll
            for (int mt = 0; mt < 2; ++mt)
#pragma unroll
                for (int nt = 0; nt < 4; ++nt) {
                    d[mt][nt][0] = bias0[mt]; d[mt][nt][1] = bias0[mt];
                    d[mt][nt][2] = bias1[mt]; d[mt][nt][3] = bias1[mt];
                }
            const uint32_t bX_hi = sb + XBUF(sx) + khoff + b_off;
            const uint32_t bX_lo = bX_hi + 4608;
#pragma unroll
            for (int ks = 0; ks < 2; ++ks) {     // K-half: 2 x k16
                uint32_t alo[2][4], bh[2][4], bl[2][4];
                ldm_x4(alo[0], aW_lo + ks * 32);
                ldm_x4(alo[1], aW_lo + 16 * ROWB + ks * 32);
                ldm_x4(bh[0], bX_hi + ks * 32);
                ldm_x4(bh[1], bX_hi + 16 * ROWB + ks * 32);
                ldm_x4(bl[0], bX_lo + ks * 32);
                ldm_x4(bl[1], bX_lo + 16 * ROWB + ks * 32);
#pragma unroll
                for (int mt = 0; mt < 2; ++mt)
#pragma unroll
                    for (int nt = 0; nt < 4; ++nt) {
                        const uint32_t* bhp = &bh[nt >> 1][(nt & 1) * 2];
                        const uint32_t* blp = &bl[nt >> 1][(nt & 1) * 2];
                        mma_bf16(d[mt][nt], Ahi[mt][ks], bhp);
                        mma_bf16(d[mt][nt], Ahi[mt][ks], blp);
                        mma_bf16(d[mt][nt], alo[mt], bhp);
                    }
            }
            BAR_ARRIVE(8 + sx);                  // x slot free (LDSM done)

            if (i >= 2) BAR_SYNC(3 + sf);        // wait ff slot free (ring 2)

            // store partial ff into this K-half's plane, [t][h] stride 132
            {
                float* ffp = reinterpret_cast<float*>(smem + FFB(sf) + kh * FF_PLANE);
                const int baser = mw * 32 + r0;
#pragma unroll
                for (int mt = 0; mt < 2; ++mt) {
                    const int row = baser + mt * 16;
#pragma unroll
                    for (int nt = 0; nt < 4; ++nt) {
                        const int col = nt * 8 + c0;
                        ffp[col * FF_STR + row]           = d[mt][nt][0];
                        ffp[(col + 1) * FF_STR + row]     = d[mt][nt][1];
                        ffp[col * FF_STR + row + 8]       = d[mt][nt][2];
                        ffp[(col + 1) * FF_STR + row + 8] = d[mt][nt][3];
                    }
                }
            }
            BAR_ARRIVE(1 + sf);                  // ff tile ready

            if (++sx == 3) sx = 0;
            sf ^= 1;
        }
    } else {
        // ==================== CONSUMERS (scan + x feed) ====================
        const int h  = tid;
        const int ct = tid;
        float* outp = out + (size_t)b * T_DIM * H_DIM + h;

        // prologue: convert x tiles 0,1 into slots 0,1; prefetch tile 2
        float4 xr[4];
        {
            const float4* x4 = reinterpret_cast<const float4*>(xb);
#pragma unroll
            for (int q = 0; q < 4; ++q) xr[q] = __ldg(&x4[ct + (q << 7)]);
            convert_to_slot(smem, 0, ct, xr);
            BAR_ARRIVE(5 + 0);
            x4 = reinterpret_cast<const float4*>(xb + (size_t)TILE_T * K_DIM);
#pragma unroll
            for (int q = 0; q < 4; ++q) xr[q] = __ldg(&x4[ct + (q << 7)]);
            convert_to_slot(smem, 1, ct, xr);
            BAR_ARRIVE(5 + 1);
            x4 = reinterpret_cast<const float4*>(xb + (size_t)2 * TILE_T * K_DIM);
#pragma unroll
            for (int q = 0; q < 4; ++q) xr[q] = __ldg(&x4[ct + (q << 7)]);
        }

        // scan state: z = 0.9*y_{-1} - 1.25*th_{-1} = -1.0 (mem=0, spk=0)
        float z = -1.0f;
        int sf = 0, sx = 2;                      // next convert slot = tile 2

        for (int i = 0; i < N_TILES; ++i) {
            // convert tile i+2 (regs loaded last iter), then prefetch i+3
            if (i + 2 < N_TILES) {
                if (i + 2 >= 3) BAR_SYNC(8 + sx);
                convert_to_slot(smem, sx, ct, xr);
                BAR_ARRIVE(5 + sx);
                if (++sx == 3) sx = 0;
            }
            if (i + 3 < N_TILES) {
                const float4* x4 = reinterpret_cast<const float4*>(
                    xb + (size_t)(i + 3) * TILE_T * K_DIM);
#pragma unroll
                for (int q = 0; q < 4; ++q) xr[q] = __ldg(&x4[ct + (q << 7)]);
            }

            BAR_SYNC(1 + sf);                    // wait ff tile i (both halves)
            const float* fpA = reinterpret_cast<const float*>(smem + FFB(sf)) + h;
            const float* fpB = fpA + FF_PLANE / 4;   // second K-half plane
            float g[TILE_T];
#pragma unroll
            for (int t = 0; t < TILE_T; ++t)
                g[t] = fpA[t * FF_STR] + fpB[t * FF_STR];
            BAR_ARRIVE(3 + sf);                  // free ff slot immediately
            sf ^= 1;

            float* po = outp + (size_t)i * TILE_T * H_DIM;
            float y = z + g[0];
#pragma unroll
            for (int t = 0; t < TILE_T; ++t) {
                float th = tanhf_approx(y);          // MUFU (critical path)
                float gn = (t < TILE_T - 1) ? g[t + 1] : 0.0f;
                float a  = fmaf(0.9f, y, gn);        // parallel with tanh
                y = fmaf(th, -1.25f, a);             // y_{t+1} (or z at t=31)
                float spk = fmaf(th, 0.5f, 0.5f);    // off critical path
                po[(size_t)t * H_DIM] = spk;
            }
            z = y;                               // carry partial to next tile
        }
    }
}

// ============================================================================
// Launch. Inputs: x [256,2048,64] f32, W [128,64] f32, b [128] f32 -> out f32
// ============================================================================
extern "C" void kernel_launch(void* const* d_in, const int* in_sizes, int n_in,
                              void* d_out, int out_size) {
    const float* x = (const float*)d_in[0];
    const float* W = (const float*)d_in[1];
    const float* b = (const float*)d_in[2];
    float* out = (float*)d_out;

    cudaFuncSetAttribute(snn_encoder_kernel,
                         cudaFuncAttributeMaxDynamicSharedMemorySize, SMEM_TOTAL);
    snn_encoder_kernel<<<B_DIM, 384, SMEM_TOTAL>>>(x, W, b, out);
}